// round 2
// baseline (speedup 1.0000x reference)
#include <cuda_runtime.h>
#include <math.h>

// YOLOv1 loss, fully fused single kernel.
// Algebraic simplification: max_iou only compared to 0 and union>0 always,
// so cmask == "exists masked pred box with intersection > 0". Intersection
// arithmetic replicates reference ops exactly (0.5f*w halving, min/max/sub),
// so the >0 decision is bit-identical to the reference's iou>0.
//
// Single launch: per-CTA partials -> g_part (every slot overwritten each run),
// threadfence + atomic counter; last CTA reduces in double, writes out, and
// resets the counter to 0 (so every graph replay starts from counter==0).

#define CELLS 49
#define CH 30
#define FPS (CELLS * CH)   // 1470 floats per sample
#define TPB 256
#define MAXCTA 8192

__device__ float g_part[MAXCTA * 4];
__device__ unsigned int g_count = 0;

__global__ __launch_bounds__(TPB) void yolo_fused_kernel(
    const float* __restrict__ pred, const float* __restrict__ target,
    float* __restrict__ out, int B, int ncta)
{
    __shared__ float sp[2 * FPS];
    __shared__ float st[2 * FPS];
    __shared__ int s_cells[2][CELLS];
    __shared__ int s_ncells[2];
    __shared__ float s_red[4][TPB / 32];
    __shared__ int s_last;

    const int tid = threadIdx.x;
    const int b0 = blockIdx.x * 2;
    const int nsamp = min(2, B - b0);

    if (tid < 2) s_ncells[tid] = 0;

    // ---- staging: 2 samples = 2940 floats = 735 float4 per tensor ----
    if (nsamp == 2) {
        const float4* gp = (const float4*)(pred + (size_t)b0 * FPS);
        const float4* gt = (const float4*)(target + (size_t)b0 * FPS);
        float4* sp4 = (float4*)sp;
        float4* st4 = (float4*)st;
        #pragma unroll 3
        for (int i = tid; i < (2 * FPS) / 4; i += TPB) {
            sp4[i] = gp[i];
            st4[i] = gt[i];
        }
    } else {  // odd tail sample: float2 path (5880 B stride is 8B aligned)
        const float2* gp = (const float2*)(pred + (size_t)b0 * FPS);
        const float2* gt = (const float2*)(target + (size_t)b0 * FPS);
        float2* sp2 = (float2*)sp;
        float2* st2 = (float2*)st;
        for (int i = tid; i < FPS / 2; i += TPB) {
            sp2[i] = gp[i];
            st2[i] = gt[i];
        }
    }
    __syncthreads();

    float noobj = 0.f, cls = 0.f, coord = 0.f, objc = 0.f;

    // ---- phase 1: per-cell noobj / class terms + obj-cell compaction ----
    if (tid < nsamp * CELLS) {
        const int s = (tid >= CELLS) ? 1 : 0;
        const int c = tid - s * CELLS;
        const float* tc = st + s * FPS + c * CH;
        const float* pc = sp + s * FPS + c * CH;
        if (tc[4] == 0.f) {  // conf channel is exactly 0 or 1
            float d4 = pc[4] - tc[4];
            float d9 = pc[9] - tc[9];
            noobj = d4 * d4 + d9 * d9;
        } else {
            float acc = 0.f;
            #pragma unroll
            for (int k = 10; k < CH; k++) {
                float d = pc[k] - tc[k];
                acc += d * d;
            }
            cls = acc;
            s_cells[s][atomicAdd(&s_ncells[s], 1)] = c;
        }
    }
    __syncthreads();

    // ---- phase 2: per obj box — overlap existence + coord/conf losses ----
    {
        const int s = tid >> 7;          // threads 0-127 -> sample 0, 128-255 -> sample 1
        const int i = tid & 127;
        const int nbox = (s < nsamp) ? 2 * s_ncells[s] : 0;
        if (i < nbox) {
            const float* base_p = sp + s * FPS;
            const float* base_t = st + s * FPS;
            const int off = s_cells[s][i >> 1] * CH + 5 * (i & 1);
            const float* tb = base_t + off;
            const float tcx = tb[0], tcy = tb[1], tw = tb[2], th = tb[3];
            const float tx0 = tcx - 0.5f * tw, ty0 = tcy - 0.5f * th;
            const float tx1 = tcx + 0.5f * tw, ty1 = tcy + 0.5f * th;

            bool found = false;
            for (int j = 0; j < nbox; j++) {
                const int po = s_cells[s][j >> 1] * CH + 5 * (j & 1);
                const float pcx = base_p[po], pcy = base_p[po + 1];
                const float pw = base_p[po + 2], ph = base_p[po + 3];
                const float ix = fminf(pcx + 0.5f * pw, tx1) - fmaxf(pcx - 0.5f * pw, tx0);
                const float iy = fminf(pcy + 0.5f * ph, ty1) - fmaxf(pcy - 0.5f * ph, ty0);
                if (ix > 0.f && iy > 0.f && ix * iy > 0.f) { found = true; break; }
            }
            if (found) {
                const float* pb = base_p + off;
                const float dx = pb[0] - tb[0];
                const float dy = pb[1] - tb[1];
                const float dw = sqrtf(pb[2]) - sqrtf(tb[2]);
                const float dh = sqrtf(pb[3]) - sqrtf(tb[3]);
                coord = dx * dx + dy * dy + dw * dw + dh * dh;
                const float dc = pb[4] - tb[4];
                objc = dc * dc;
            }
        }
    }

    // ---- block reduction of 4 scalars over 256 threads ----
    #pragma unroll
    for (int o = 16; o > 0; o >>= 1) {
        noobj += __shfl_down_sync(0xffffffffu, noobj, o);
        cls   += __shfl_down_sync(0xffffffffu, cls, o);
        coord += __shfl_down_sync(0xffffffffu, coord, o);
        objc  += __shfl_down_sync(0xffffffffu, objc, o);
    }
    const int warp = tid >> 5, lane = tid & 31;
    if (lane == 0) {
        s_red[0][warp] = noobj;
        s_red[1][warp] = cls;
        s_red[2][warp] = coord;
        s_red[3][warp] = objc;
    }
    __syncthreads();

    if (tid == 0) {
        float p0 = 0.f, p1 = 0.f, p2 = 0.f, p3 = 0.f;
        #pragma unroll
        for (int w = 0; w < TPB / 32; w++) {
            p0 += s_red[0][w];
            p1 += s_red[1][w];
            p2 += s_red[2][w];
            p3 += s_red[3][w];
        }
        float* dst = g_part + blockIdx.x * 4;
        dst[0] = p0; dst[1] = p1; dst[2] = p2; dst[3] = p3;
        __threadfence();
        unsigned int old = atomicAdd(&g_count, 1u);
        s_last = (old == (unsigned int)(ncta - 1)) ? 1 : 0;
    }
    __syncthreads();

    // ---- last CTA: final reduction (fixed order -> deterministic) ----
    if (s_last) {
        double a0 = 0.0, a1 = 0.0, a2 = 0.0, a3 = 0.0;
        for (int i = tid; i < ncta; i += TPB) {
            const float* src = g_part + i * 4;
            a0 += (double)src[0];
            a1 += (double)src[1];
            a2 += (double)src[2];
            a3 += (double)src[3];
        }
        #pragma unroll
        for (int o = 16; o > 0; o >>= 1) {
            a0 += __shfl_down_sync(0xffffffffu, a0, o);
            a1 += __shfl_down_sync(0xffffffffu, a1, o);
            a2 += __shfl_down_sync(0xffffffffu, a2, o);
            a3 += __shfl_down_sync(0xffffffffu, a3, o);
        }
        __shared__ double s_d[4][TPB / 32];
        if (lane == 0) {
            s_d[0][warp] = a0; s_d[1][warp] = a1;
            s_d[2][warp] = a2; s_d[3][warp] = a3;
        }
        __syncthreads();
        if (tid == 0) {
            double r0 = 0, r1 = 0, r2 = 0, r3 = 0;
            #pragma unroll
            for (int w = 0; w < TPB / 32; w++) {
                r0 += s_d[0][w]; r1 += s_d[1][w];
                r2 += s_d[2][w]; r3 += s_d[3][w];
            }
            const double inv = 1.0 / (double)B;
            const double cls_l = r1 * inv;                 // class
            const double obj_l = (r3 + 0.5 * r0) * inv;    // obj + 0.5*noobj
            const double crd_l = r2 * 5.0 * inv;           // coord * 5
            out[0] = (float)(cls_l + obj_l + crd_l);
            out[1] = (float)cls_l;
            out[2] = (float)obj_l;
            out[3] = (float)crd_l;
            g_count = 0u;  // restore initial state for next graph replay
        }
    }
}

extern "C" void kernel_launch(void* const* d_in, const int* in_sizes, int n_in,
                              void* d_out, int out_size)
{
    const float* pred = (const float*)d_in[0];
    const float* target = (const float*)d_in[1];
    const int B = in_sizes[0] / FPS;
    const int ncta = (B + 1) / 2;

    yolo_fused_kernel<<<ncta, TPB>>>(pred, target, (float*)d_out, B, ncta);
}